// round 16
// baseline (speedup 1.0000x reference)
#include <cuda_runtime.h>
#include <cuda_bf16.h>
#include <cstdint>
#include <math.h>

#define NN 50000
#define EE 800000

// ---------------- scratch (static device globals) ---------------------------
static __device__ __align__(16) __nv_bfloat16 g_Ah[(size_t)NN * 768];
static __device__ __align__(16) __nv_bfloat16 g_Al[(size_t)NN * 768];
static __device__ __align__(16) float         g_C[(size_t)NN * 640];
#define WTOT 1146880
static __device__ __align__(16) __nv_bfloat16 g_Wh[WTOT];
static __device__ __align__(16) __nv_bfloat16 g_Wl[WTOT];
static __device__ float g_S[(size_t)NN * 10];
static __device__ int   g_cnt[NN];
static __device__ int   g_cursor[NN];
static __device__ int   g_off[NN + 1];
static __device__ int   g_csr[EE];
static __device__ float g_nrm[EE];
static __device__ float g_dis[NN];

__device__ __forceinline__ uint32_t sm_u32(const void* p) {
    uint32_t a;
    asm("{ .reg .u64 t; cvta.to.shared.u64 t, %1; cvt.u32.u64 %0, t; }"
        : "=r"(a) : "l"(p));
    return a;
}

// ---------------- streams/events (created pre-main, outside capture) ---------
struct HxStreams {
    cudaStream_t s1, s2;
    cudaEvent_t eFork, eCsr, eWT;
    HxStreams() {
        cudaStreamCreateWithFlags(&s1, cudaStreamNonBlocking);
        cudaStreamCreateWithFlags(&s2, cudaStreamNonBlocking);
        cudaEventCreateWithFlags(&eFork, cudaEventDisableTiming);
        cudaEventCreateWithFlags(&eCsr,  cudaEventDisableTiming);
        cudaEventCreateWithFlags(&eWT,   cudaEventDisableTiming);
    }
};
static HxStreams hx;

// ---------------- CSR build --------------------------------------------------
__global__ void k_zero() {
    int i = blockIdx.x * blockDim.x + threadIdx.x;
    if (i < NN) { g_cnt[i] = 0; g_cursor[i] = 0; }
}
__global__ void k_hist(const int* __restrict__ ei) {
    int e = blockIdx.x * blockDim.x + threadIdx.x;
    if (e < EE) atomicAdd(&g_cnt[ei[EE + e]], 1);
}
__global__ void k_scan() {
    __shared__ int sh[1024];
    const int CH = (NN + 1023) / 1024;
    int t = threadIdx.x;
    int beg = t * CH, end = beg + CH; if (end > NN) end = NN;
    int s = 0;
    for (int i = beg; i < end; i++) s += g_cnt[i];
    sh[t] = s;
    __syncthreads();
    for (int off = 1; off < 1024; off <<= 1) {
        int v = (t >= off) ? sh[t - off] : 0;
        __syncthreads();
        sh[t] += v;
        __syncthreads();
    }
    int run = (t == 0) ? 0 : sh[t - 1];
    for (int i = beg; i < end; i++) { g_off[i] = run; run += g_cnt[i]; }
    if (t == 1023) g_off[NN] = sh[1023];
    for (int i = beg; i < end; i++) g_dis[i] = rsqrtf((float)(g_cnt[i] + 1));
}
__global__ void k_scatter(const int* __restrict__ ei) {
    int e = blockIdx.x * blockDim.x + threadIdx.x;
    if (e < EE) {
        int s = ei[e], d = ei[EE + e];
        int p = atomicAdd(&g_cursor[d], 1);
        int pos = g_off[d] + p;
        g_csr[pos] = s;
        g_nrm[pos] = g_dis[s] * g_dis[d];
    }
}

// ---------------- input pad+split --------------------------------------------
__global__ void k_pad(const float* __restrict__ x) {
    int idx = blockIdx.x * blockDim.x + threadIdx.x;
    if (idx >= NN * 192) return;
    int m = idx / 192, j = idx - m * 192;
    int c0 = j * 4;
    float v[4];
    #pragma unroll
    for (int i = 0; i < 4; i++) {
        int c = c0 + i;
        v[i] = (c < 767) ? x[(size_t)m * 767 + c] : 0.f;
    }
    __nv_bfloat162 h0, h1, l0, l1;
    h0.x = __float2bfloat16_rn(v[0]); h0.y = __float2bfloat16_rn(v[1]);
    h1.x = __float2bfloat16_rn(v[2]); h1.y = __float2bfloat16_rn(v[3]);
    l0.x = __float2bfloat16_rn(v[0] - __bfloat162float(h0.x));
    l0.y = __float2bfloat16_rn(v[1] - __bfloat162float(h0.y));
    l1.x = __float2bfloat16_rn(v[2] - __bfloat162float(h1.x));
    l1.y = __float2bfloat16_rn(v[3] - __bfloat162float(h1.y));
    size_t o = (size_t)m * 768 + c0;
    *(__nv_bfloat162*)(g_Ah + o)     = h0;
    *(__nv_bfloat162*)(g_Ah + o + 2) = h1;
    *(__nv_bfloat162*)(g_Al + o)     = l0;
    *(__nv_bfloat162*)(g_Al + o + 2) = l1;
}

// ---------------- all-layer weight transpose+pad+split -----------------------
struct WPtrs { const float* p[5]; };
__constant__ const int c_K[5]  = {767, 640, 512, 384, 256};
__constant__ const int c_Nc[5] = {640, 512, 384, 256, 128};
__constant__ const int c_KP[5] = {768, 640, 512, 384, 256};
__constant__ const int c_WO[6] = {0, 491520, 819200, 1015808, 1114112, 1146880};

__global__ void k_wT_all(WPtrs wp) {
    int idx = blockIdx.x * blockDim.x + threadIdx.x;
    if (idx >= WTOT) return;
    int l = 0;
    if (idx >= c_WO[1]) l = 1;
    if (idx >= c_WO[2]) l = 2;
    if (idx >= c_WO[3]) l = 3;
    if (idx >= c_WO[4]) l = 4;
    int local = idx - c_WO[l];
    int KP = c_KP[l], Nc = c_Nc[l], K = c_K[l];
    int n = local / KP, k = local - n * KP;
    float v = (k < K) ? wp.p[l][(size_t)k * Nc + n] : 0.f;
    __nv_bfloat16 h = __float2bfloat16_rn(v);
    g_Wh[idx] = h;
    g_Wl[idx] = __float2bfloat16_rn(v - __bfloat162float(h));
}

// ---------------- bf16x3 tensor-core GEMM ------------------------------------
#define PIPE 3
#define TILE_B 8192
#define STAGE_B (4 * TILE_B)
#define SMEM_MM (PIPE * STAGE_B)

__device__ __forceinline__ void cp16(uint32_t d, const void* s, int n) {
    asm volatile("cp.async.cg.shared.global [%0], [%1], 16, %2;\n"
                 :: "r"(d), "l"(s), "r"(n));
}
__device__ __forceinline__ void mma_bf16(float* d, const uint32_t* a, const uint32_t* b) {
    asm volatile(
        "mma.sync.aligned.m16n8k16.row.col.f32.bf16.bf16.f32 "
        "{%0,%1,%2,%3}, {%4,%5,%6,%7}, {%8,%9}, {%0,%1,%2,%3};"
        : "+f"(d[0]), "+f"(d[1]), "+f"(d[2]), "+f"(d[3])
        : "r"(a[0]), "r"(a[1]), "r"(a[2]), "r"(a[3]), "r"(b[0]), "r"(b[1]));
}
__device__ __forceinline__ void ldm_x4(uint32_t* r, uint32_t a) {
    asm volatile("ldmatrix.sync.aligned.m8n8.x4.shared.b16 {%0,%1,%2,%3}, [%4];"
                 : "=r"(r[0]), "=r"(r[1]), "=r"(r[2]), "=r"(r[3]) : "r"(a));
}
__device__ __forceinline__ uint32_t swzo(int row, int chunk) {
    return (uint32_t)(row * 64 + ((chunk ^ ((row >> 1) & 3)) * 16));
}

__global__ __launch_bounds__(256, 2) void k_mm(
    const __nv_bfloat16* __restrict__ Ah, const __nv_bfloat16* __restrict__ Al,
    const __nv_bfloat16* __restrict__ Wh, const __nv_bfloat16* __restrict__ Wl,
    float* __restrict__ C, int M, int KP, int Nc)
{
    extern __shared__ __nv_bfloat16 smem[];
    uint32_t sb = sm_u32(smem);
    int tid = threadIdx.x, lane = tid & 31, wid = tid >> 5;
    int wm = wid >> 2, wn = wid & 3;
    int m0 = blockIdx.y * 128, n0 = blockIdx.x * 128;
    const int NC = KP >> 5;
    int lr = lane >> 2, lc = (lane & 3) * 2;

    int rbA = wm * 64 + (lane & 15);
    int csA = lane >> 4;
    uint32_t offA0 = swzo(rbA, csA);
    uint32_t offA1 = swzo(rbA, 2 + csA);
    int rbB = wn * 32 + (lane & 7) + ((lane >> 4) & 1) * 8;
    int csB = (lane >> 3) & 1;
    uint32_t offB[2][2];
    #pragma unroll
    for (int kh = 0; kh < 2; kh++)
        #pragma unroll
        for (int nfp = 0; nfp < 2; nfp++)
            offB[kh][nfp] = swzo(rbB + nfp * 16, csB + kh * 2);

    int row = tid >> 1;
    int q0 = (tid & 1) * 2;
    int gm = m0 + row;
    int aok = (gm < M) ? 16 : 0;
    int gmc = (gm < M) ? gm : (M - 1);
    const __nv_bfloat16* pAh = Ah + (size_t)gmc * KP + q0 * 8;
    const __nv_bfloat16* pAl = Al + (size_t)gmc * KP + q0 * 8;
    const __nv_bfloat16* pBh = Wh + (size_t)(n0 + row) * KP + q0 * 8;
    const __nv_bfloat16* pBl = Wl + (size_t)(n0 + row) * KP + q0 * 8;
    uint32_t dro0 = swzo(row, q0);
    uint32_t dro1 = swzo(row, q0 + 1);

    auto issue = [&](int c) {
        int k0 = c << 5;
        uint32_t st = sb + (uint32_t)(c % PIPE) * STAGE_B;
        cp16(st + dro0,              pAh + k0,     aok);
        cp16(st + dro1,              pAh + k0 + 8, aok);
        cp16(st + TILE_B + dro0,     pAl + k0,     aok);
        cp16(st + TILE_B + dro1,     pAl + k0 + 8, aok);
        cp16(st + 2*TILE_B + dro0,   pBh + k0,     16);
        cp16(st + 2*TILE_B + dro1,   pBh + k0 + 8, 16);
        cp16(st + 3*TILE_B + dro0,   pBl + k0,     16);
        cp16(st + 3*TILE_B + dro1,   pBl + k0 + 8, 16);
    };

    float acc[4][4][4];
    #pragma unroll
    for (int i = 0; i < 4; i++)
        #pragma unroll
        for (int j = 0; j < 4; j++)
            #pragma unroll
            for (int r = 0; r < 4; r++) acc[i][j][r] = 0.f;

    issue(0);
    asm volatile("cp.async.commit_group;");
    issue(1);
    asm volatile("cp.async.commit_group;");

    for (int c = 0; c < NC; c++) {
        asm volatile("cp.async.wait_group 1;");
        __syncthreads();
        if (c + 2 < NC) issue(c + 2);
        asm volatile("cp.async.commit_group;");

        uint32_t stb = sb + (uint32_t)(c % PIPE) * STAGE_B;

        #pragma unroll
        for (int kh = 0; kh < 2; kh++) {
            uint32_t oA = kh ? offA1 : offA0;
            uint32_t bh[4][2], bl[4][2];
            #pragma unroll
            for (int nfp = 0; nfp < 2; nfp++) {
                uint32_t t[4];
                ldm_x4(t, stb + 2*TILE_B + offB[kh][nfp]);
                bh[2*nfp][0] = t[0]; bh[2*nfp][1] = t[1];
                bh[2*nfp+1][0] = t[2]; bh[2*nfp+1][1] = t[3];
                ldm_x4(t, stb + 3*TILE_B + offB[kh][nfp]);
                bl[2*nfp][0] = t[0]; bl[2*nfp][1] = t[1];
                bl[2*nfp+1][0] = t[2]; bl[2*nfp+1][1] = t[3];
            }
            #pragma unroll
            for (int mf = 0; mf < 4; mf++) {
                uint32_t mo = (uint32_t)mf * 1024;
                uint32_t ah[4], al[4];
                ldm_x4(ah, stb + oA + mo);
                ldm_x4(al, stb + TILE_B + oA + mo);
                #pragma unroll
                for (int nf = 0; nf < 4; nf++) {
                    mma_bf16(acc[mf][nf], ah, bh[nf]);
                    mma_bf16(acc[mf][nf], ah, bl[nf]);
                    mma_bf16(acc[mf][nf], al, bh[nf]);
                }
            }
        }
    }

    #pragma unroll
    for (int mf = 0; mf < 4; mf++) {
        int r0 = m0 + wm * 64 + mf * 16 + lr;
        #pragma unroll
        for (int nf = 0; nf < 4; nf++) {
            int cc = n0 + wn * 32 + nf * 8 + lc;
            if (r0 < M)
                *(float2*)(C + (size_t)r0 * Nc + cc) =
                    make_float2(acc[mf][nf][0], acc[mf][nf][1]);
            if (r0 + 8 < M)
                *(float2*)(C + (size_t)(r0 + 8) * Nc + cc) =
                    make_float2(acc[mf][nf][2], acc[mf][nf][3]);
        }
    }
}

// ---------------- aggregation -> bf16 hi/lo (2 float4 slices per thread) -----
// Thread t handles f4 columns t and t+H of F4 total (H = F4/2).
__global__ void k_aggv(const float4* __restrict__ h, const float4* __restrict__ bias,
                       __nv_bfloat162* __restrict__ oh, __nv_bfloat162* __restrict__ ol,
                       int relu, int F4)
{
    int node = blockIdx.x;
    int H = F4 >> 1;
    int t0 = threadIdx.x, t1 = threadIdx.x + H;
    float dd = g_dis[node];
    float w0 = dd * dd;
    const float4* hn = h + (size_t)node * F4;
    float4 a0 = hn[t0], a1 = hn[t1];
    float4 acc0 = make_float4(a0.x * w0, a0.y * w0, a0.z * w0, a0.w * w0);
    float4 acc1 = make_float4(a1.x * w0, a1.y * w0, a1.z * w0, a1.w * w0);
    int e = g_off[node], end = g_off[node + 1];
    for (; e + 1 < end; e += 2) {
        int s0 = g_csr[e], s1 = g_csr[e + 1];
        float u0 = g_nrm[e], u1 = g_nrm[e + 1];
        const float4* p0 = h + (size_t)s0 * F4;
        const float4* p1 = h + (size_t)s1 * F4;
        float4 v00 = p0[t0], v01 = p0[t1];
        float4 v10 = p1[t0], v11 = p1[t1];
        acc0.x = fmaf(v00.x, u0, fmaf(v10.x, u1, acc0.x));
        acc0.y = fmaf(v00.y, u0, fmaf(v10.y, u1, acc0.y));
        acc0.z = fmaf(v00.z, u0, fmaf(v10.z, u1, acc0.z));
        acc0.w = fmaf(v00.w, u0, fmaf(v10.w, u1, acc0.w));
        acc1.x = fmaf(v01.x, u0, fmaf(v11.x, u1, acc1.x));
        acc1.y = fmaf(v01.y, u0, fmaf(v11.y, u1, acc1.y));
        acc1.z = fmaf(v01.z, u0, fmaf(v11.z, u1, acc1.z));
        acc1.w = fmaf(v01.w, u0, fmaf(v11.w, u1, acc1.w));
    }
    if (e < end) {
        int s0 = g_csr[e];
        float u0 = g_nrm[e];
        const float4* p0 = h + (size_t)s0 * F4;
        float4 v00 = p0[t0], v01 = p0[t1];
        acc0.x = fmaf(v00.x, u0, acc0.x);
        acc0.y = fmaf(v00.y, u0, acc0.y);
        acc0.z = fmaf(v00.z, u0, acc0.z);
        acc0.w = fmaf(v00.w, u0, acc0.w);
        acc1.x = fmaf(v01.x, u0, acc1.x);
        acc1.y = fmaf(v01.y, u0, acc1.y);
        acc1.z = fmaf(v01.z, u0, acc1.z);
        acc1.w = fmaf(v01.w, u0, acc1.w);
    }
    #pragma unroll
    for (int s = 0; s < 2; s++) {
        int t = s ? t1 : t0;
        float4 acc = s ? acc1 : acc0;
        float4 bb = bias[t];
        float4 r = make_float4(acc.x + bb.x, acc.y + bb.y, acc.z + bb.z, acc.w + bb.w);
        if (relu) {
            r.x = fmaxf(r.x, 0.f); r.y = fmaxf(r.y, 0.f);
            r.z = fmaxf(r.z, 0.f); r.w = fmaxf(r.w, 0.f);
        }
        __nv_bfloat162 h0, h1, l0, l1;
        h0.x = __float2bfloat16_rn(r.x); h0.y = __float2bfloat16_rn(r.y);
        h1.x = __float2bfloat16_rn(r.z); h1.y = __float2bfloat16_rn(r.w);
        l0.x = __float2bfloat16_rn(r.x - __bfloat162float(h0.x));
        l0.y = __float2bfloat16_rn(r.y - __bfloat162float(h0.y));
        l1.x = __float2bfloat16_rn(r.z - __bfloat162float(h1.x));
        l1.y = __float2bfloat16_rn(r.w - __bfloat162float(h1.y));
        size_t o = ((size_t)node * F4 + t) * 2;
        oh[o] = h0; oh[o + 1] = h1;
        ol[o] = l0; ol[o + 1] = l1;
    }
}

// ---------------- fused layer-5 agg + relu + layer-6 GEMM --------------------
__global__ __launch_bounds__(256) void k_agg5(
    const float4* __restrict__ h, const float4* __restrict__ bias,
    const float* __restrict__ W6, float* __restrict__ S)
{
    __shared__ float Wt[10 * 128];            // Wt[n*128 + k] = W6[k*10 + n]
    for (int i = threadIdx.x; i < 1280; i += 256) {
        int n = i >> 7, k = i & 127;
        Wt[i] = W6[k * 10 + n];
    }
    __syncthreads();

    int w = threadIdx.x >> 5, lane = threadIdx.x & 31;
    int node = blockIdx.x * 8 + w;
    if (node >= NN) return;

    float dd = g_dis[node];
    float w0 = dd * dd;
    float4 a = h[(size_t)node * 32 + lane];
    float4 acc = make_float4(a.x * w0, a.y * w0, a.z * w0, a.w * w0);
    int e = g_off[node], end = g_off[node + 1];
    for (; e + 3 < end; e += 4) {
        int s0 = g_csr[e], s1 = g_csr[e+1], s2 = g_csr[e+2], s3 = g_csr[e+3];
        float u0 = g_nrm[e], u1 = g_nrm[e+1], u2 = g_nrm[e+2], u3 = g_nrm[e+3];
        float4 v0 = h[(size_t)s0 * 32 + lane];
        float4 v1 = h[(size_t)s1 * 32 + lane];
        float4 v2 = h[(size_t)s2 * 32 + lane];
        float4 v3 = h[(size_t)s3 * 32 + lane];
        acc.x = fmaf(v0.x, u0, fmaf(v1.x, u1, fmaf(v2.x, u2, fmaf(v3.x, u3, acc.x))));
        acc.y = fmaf(v0.y, u0, fmaf(v1.y, u1, fmaf(v2.y, u2, fmaf(v3.y, u3, acc.y))));
        acc.z = fmaf(v0.z, u0, fmaf(v1.z, u1, fmaf(v2.z, u2, fmaf(v3.z, u3, acc.z))));
        acc.w = fmaf(v0.w, u0, fmaf(v1.w, u1, fmaf(v2.w, u2, fmaf(v3.w, u3, acc.w))));
    }
    for (; e < end; e++) {
        int s0 = g_csr[e];
        float u0 = g_nrm[e];
        float4 v0 = h[(size_t)s0 * 32 + lane];
        acc.x = fmaf(v0.x, u0, acc.x);
        acc.y = fmaf(v0.y, u0, acc.y);
        acc.z = fmaf(v0.z, u0, acc.z);
        acc.w = fmaf(v0.w, u0, acc.w);
    }
    float4 bb = bias[lane];
    float4 r = make_float4(fmaxf(acc.x + bb.x, 0.f), fmaxf(acc.y + bb.y, 0.f),
                           fmaxf(acc.z + bb.z, 0.f), fmaxf(acc.w + bb.w, 0.f));

    float out = 0.f;
    #pragma unroll
    for (int n = 0; n < 10; n++) {
        float4 wv = *(const float4*)(Wt + n * 128 + lane * 4);
        float p = fmaf(r.x, wv.x, fmaf(r.y, wv.y, fmaf(r.z, wv.z, r.w * wv.w)));
        #pragma unroll
        for (int o = 16; o; o >>= 1) p += __shfl_xor_sync(0xFFFFFFFFu, p, o);
        if (lane == n) out = p;
    }
    if (lane < 10) S[(size_t)node * 10 + lane] = out;
}

// ---------------- fused final agg + log_softmax ------------------------------
__global__ void k_tail(const float* __restrict__ S, const float* __restrict__ bias,
                       float* __restrict__ out)
{
    int node = blockIdx.x;
    int f = threadIdx.x;
    bool act = f < 10;
    float dd = g_dis[node];
    float val = 0.f;
    if (act) {
        val = S[(size_t)node * 10 + f] * dd * dd;
        int e = g_off[node], end = g_off[node + 1];
        for (; e < end; e++) {
            int s = g_csr[e];
            val = fmaf(S[(size_t)s * 10 + f], g_nrm[e], val);
        }
        val += bias[f];
    }
    float m = act ? val : -1e30f;
    #pragma unroll
    for (int o = 16; o; o >>= 1) m = fmaxf(m, __shfl_xor_sync(0xFFFFFFFFu, m, o));
    float ex = act ? __expf(val - m) : 0.f;
    #pragma unroll
    for (int o = 16; o; o >>= 1) ex += __shfl_xor_sync(0xFFFFFFFFu, ex, o);
    if (act) out[(size_t)node * 10 + f] = val - m - __logf(ex);
}

// ---------------- driver -----------------------------------------------------
extern "C" void kernel_launch(void* const* d_in, const int* in_sizes, int n_in,
                              void* d_out, int out_size)
{
    const float* x  = (const float*)d_in[0];
    const int*   ei = (const int*)d_in[1];
    const float* W[6]; const float* b[6];
    for (int i = 0; i < 6; i++) {
        W[i] = (const float*)d_in[2 + 2 * i];
        b[i] = (const float*)d_in[3 + 2 * i];
    }

    __nv_bfloat16 *Ah, *Al, *Wh, *Wl;
    float *C, *S;
    cudaGetSymbolAddress((void**)&Ah, g_Ah);
    cudaGetSymbolAddress((void**)&Al, g_Al);
    cudaGetSymbolAddress((void**)&Wh, g_Wh);
    cudaGetSymbolAddress((void**)&Wl, g_Wl);
    cudaGetSymbolAddress((void**)&C,  g_C);
    cudaGetSymbolAddress((void**)&S,  g_S);

    cudaFuncSetAttribute(k_mm, cudaFuncAttributeMaxDynamicSharedMemorySize, SMEM_MM);

    const int dims[7] = {767, 640, 512, 384, 256, 128, 10};
    const int KPs[6]  = {768, 640, 512, 384, 256, 128};
    const int WO[5]   = {0, 491520, 819200, 1015808, 1114112};

    cudaEventRecord(hx.eFork, 0);

    // 1: pad (main)
    k_pad<<<(NN * 192 + 255) / 256, 256>>>(x);

    // 2: weights (s2)
    cudaStreamWaitEvent(hx.s2, hx.eFork, 0);
    WPtrs wp; for (int i = 0; i < 5; i++) wp.p[i] = W[i];
    k_wT_all<<<(WTOT + 255) / 256, 256, 0, hx.s2>>>(wp);
    cudaEventRecord(hx.eWT, hx.s2);

    // 3: CSR zero (s1)
    cudaStreamWaitEvent(hx.s1, hx.eFork, 0);
    k_zero<<<(NN + 255) / 256, 256, 0, hx.s1>>>();

    // 4: layer-1 GEMM (main; overlaps CSR chain)
    cudaStreamWaitEvent(0, hx.eWT, 0);
    {
        dim3 grid(640 / 128, (NN + 127) / 128);
        k_mm<<<grid, 256, SMEM_MM>>>(Ah, Al, Wh + WO[0], Wl + WO[0], C, NN, 768, 640);
    }

    // CSR chain (s1) — overlaps with layer-1 GEMM
    k_hist   <<<(EE + 255) / 256, 256, 0, hx.s1>>>(ei);
    k_scan   <<<1, 1024, 0, hx.s1>>>();
    k_scatter<<<(EE + 255) / 256, 256, 0, hx.s1>>>(ei);
    cudaEventRecord(hx.eCsr, hx.s1);

    // aggregation layer 1 (needs CSR) — 2 f4 slices per thread
    cudaStreamWaitEvent(0, hx.eCsr, 0);
    k_aggv<<<NN, 640 / 8>>>((const float4*)C, (const float4*)b[0],
                            (__nv_bfloat162*)Ah, (__nv_bfloat162*)Al, 1, 640 / 4);

    // layers 2-4: GEMM + aggv (hi/lo activations)
    for (int l = 1; l < 4; l++) {
        int F = dims[l + 1], KP = KPs[l];
        dim3 grid(F / 128, (NN + 127) / 128);
        k_mm<<<grid, 256, SMEM_MM>>>(Ah, Al, Wh + WO[l], Wl + WO[l], C, NN, KP, F);
        k_aggv<<<NN, F / 8>>>((const float4*)C, (const float4*)b[l],
                              (__nv_bfloat162*)Ah, (__nv_bfloat162*)Al, 1, F / 4);
    }
    // layer 5 GEMM (K=256 -> F=128)
    {
        dim3 grid(1, (NN + 127) / 128);
        k_mm<<<grid, 256, SMEM_MM>>>(Ah, Al, Wh + WO[4], Wl + WO[4], C, NN, 256, 128);
    }
    // fused: layer-5 agg + relu + layer-6 GEMM -> S
    k_agg5<<<(NN + 7) / 8, 256>>>((const float4*)C, (const float4*)b[4], W[5], S);
    // final: agg(S) + bias6 + log_softmax
    k_tail<<<NN, 32>>>(S, b[5], (float*)d_out);
}

// round 17
// speedup vs baseline: 1.0821x; 1.0821x over previous
#include <cuda_runtime.h>
#include <cuda_bf16.h>
#include <cstdint>
#include <math.h>

#define NN 50000
#define EE 800000

// ---------------- scratch (static device globals) ---------------------------
static __device__ __align__(16) __nv_bfloat16 g_Ah[(size_t)NN * 768];
static __device__ __align__(16) __nv_bfloat16 g_Al[(size_t)NN * 768];
static __device__ __align__(16) float         g_C[(size_t)NN * 640];
#define WTOT 1146880
static __device__ __align__(16) __nv_bfloat16 g_Wh[WTOT];
static __device__ __align__(16) __nv_bfloat16 g_Wl[WTOT];
static __device__ float g_S[(size_t)NN * 10];
static __device__ int   g_cnt[NN];
static __device__ int   g_cursor[NN];
static __device__ int   g_off[NN + 1];
static __device__ int   g_csr[EE];
static __device__ float g_nrm[EE];
static __device__ float g_dis[NN];

__device__ __forceinline__ uint32_t sm_u32(const void* p) {
    uint32_t a;
    asm("{ .reg .u64 t; cvta.to.shared.u64 t, %1; cvt.u32.u64 %0, t; }"
        : "=r"(a) : "l"(p));
    return a;
}

// ---------------- streams/events (created pre-main, outside capture) ---------
struct HxStreams {
    cudaStream_t s1, s2;
    cudaEvent_t eFork, eCsr, eWT;
    HxStreams() {
        cudaStreamCreateWithFlags(&s1, cudaStreamNonBlocking);
        cudaStreamCreateWithFlags(&s2, cudaStreamNonBlocking);
        cudaEventCreateWithFlags(&eFork, cudaEventDisableTiming);
        cudaEventCreateWithFlags(&eCsr,  cudaEventDisableTiming);
        cudaEventCreateWithFlags(&eWT,   cudaEventDisableTiming);
    }
};
static HxStreams hx;

// ---------------- CSR build --------------------------------------------------
__global__ void k_zero() {
    int i = blockIdx.x * blockDim.x + threadIdx.x;
    if (i < NN) { g_cnt[i] = 0; g_cursor[i] = 0; }
}
__global__ void k_hist(const int* __restrict__ ei) {
    int e = blockIdx.x * blockDim.x + threadIdx.x;
    if (e < EE) atomicAdd(&g_cnt[ei[EE + e]], 1);
}
__global__ void k_scan() {
    __shared__ int sh[1024];
    const int CH = (NN + 1023) / 1024;
    int t = threadIdx.x;
    int beg = t * CH, end = beg + CH; if (end > NN) end = NN;
    int s = 0;
    for (int i = beg; i < end; i++) s += g_cnt[i];
    sh[t] = s;
    __syncthreads();
    for (int off = 1; off < 1024; off <<= 1) {
        int v = (t >= off) ? sh[t - off] : 0;
        __syncthreads();
        sh[t] += v;
        __syncthreads();
    }
    int run = (t == 0) ? 0 : sh[t - 1];
    for (int i = beg; i < end; i++) { g_off[i] = run; run += g_cnt[i]; }
    if (t == 1023) g_off[NN] = sh[1023];
    for (int i = beg; i < end; i++) g_dis[i] = rsqrtf((float)(g_cnt[i] + 1));
}
__global__ void k_scatter(const int* __restrict__ ei) {
    int e = blockIdx.x * blockDim.x + threadIdx.x;
    if (e < EE) {
        int s = ei[e], d = ei[EE + e];
        int p = atomicAdd(&g_cursor[d], 1);
        int pos = g_off[d] + p;
        g_csr[pos] = s;
        g_nrm[pos] = g_dis[s] * g_dis[d];
    }
}

// ---------------- input pad+split --------------------------------------------
__global__ void k_pad(const float* __restrict__ x) {
    int idx = blockIdx.x * blockDim.x + threadIdx.x;
    if (idx >= NN * 192) return;
    int m = idx / 192, j = idx - m * 192;
    int c0 = j * 4;
    float v[4];
    #pragma unroll
    for (int i = 0; i < 4; i++) {
        int c = c0 + i;
        v[i] = (c < 767) ? x[(size_t)m * 767 + c] : 0.f;
    }
    __nv_bfloat162 h0, h1, l0, l1;
    h0.x = __float2bfloat16_rn(v[0]); h0.y = __float2bfloat16_rn(v[1]);
    h1.x = __float2bfloat16_rn(v[2]); h1.y = __float2bfloat16_rn(v[3]);
    l0.x = __float2bfloat16_rn(v[0] - __bfloat162float(h0.x));
    l0.y = __float2bfloat16_rn(v[1] - __bfloat162float(h0.y));
    l1.x = __float2bfloat16_rn(v[2] - __bfloat162float(h1.x));
    l1.y = __float2bfloat16_rn(v[3] - __bfloat162float(h1.y));
    size_t o = (size_t)m * 768 + c0;
    *(__nv_bfloat162*)(g_Ah + o)     = h0;
    *(__nv_bfloat162*)(g_Ah + o + 2) = h1;
    *(__nv_bfloat162*)(g_Al + o)     = l0;
    *(__nv_bfloat162*)(g_Al + o + 2) = l1;
}

// ---------------- all-layer weight transpose+pad+split -----------------------
struct WPtrs { const float* p[5]; };
__constant__ const int c_K[5]  = {767, 640, 512, 384, 256};
__constant__ const int c_Nc[5] = {640, 512, 384, 256, 128};
__constant__ const int c_KP[5] = {768, 640, 512, 384, 256};
__constant__ const int c_WO[6] = {0, 491520, 819200, 1015808, 1114112, 1146880};

__global__ void k_wT_all(WPtrs wp) {
    int idx = blockIdx.x * blockDim.x + threadIdx.x;
    if (idx >= WTOT) return;
    int l = 0;
    if (idx >= c_WO[1]) l = 1;
    if (idx >= c_WO[2]) l = 2;
    if (idx >= c_WO[3]) l = 3;
    if (idx >= c_WO[4]) l = 4;
    int local = idx - c_WO[l];
    int KP = c_KP[l], Nc = c_Nc[l], K = c_K[l];
    int n = local / KP, k = local - n * KP;
    float v = (k < K) ? wp.p[l][(size_t)k * Nc + n] : 0.f;
    __nv_bfloat16 h = __float2bfloat16_rn(v);
    g_Wh[idx] = h;
    g_Wl[idx] = __float2bfloat16_rn(v - __bfloat162float(h));
}

// ---------------- bf16x3 tensor-core GEMM ------------------------------------
#define PIPE 3
#define TILE_B 8192
#define STAGE_B (4 * TILE_B)
#define SMEM_MM (PIPE * STAGE_B)

__device__ __forceinline__ void cp16(uint32_t d, const void* s, int n) {
    asm volatile("cp.async.cg.shared.global [%0], [%1], 16, %2;\n"
                 :: "r"(d), "l"(s), "r"(n));
}
__device__ __forceinline__ void mma_bf16(float* d, const uint32_t* a, const uint32_t* b) {
    asm volatile(
        "mma.sync.aligned.m16n8k16.row.col.f32.bf16.bf16.f32 "
        "{%0,%1,%2,%3}, {%4,%5,%6,%7}, {%8,%9}, {%0,%1,%2,%3};"
        : "+f"(d[0]), "+f"(d[1]), "+f"(d[2]), "+f"(d[3])
        : "r"(a[0]), "r"(a[1]), "r"(a[2]), "r"(a[3]), "r"(b[0]), "r"(b[1]));
}
__device__ __forceinline__ void ldm_x4(uint32_t* r, uint32_t a) {
    asm volatile("ldmatrix.sync.aligned.m8n8.x4.shared.b16 {%0,%1,%2,%3}, [%4];"
                 : "=r"(r[0]), "=r"(r[1]), "=r"(r[2]), "=r"(r[3]) : "r"(a));
}
__device__ __forceinline__ uint32_t swzo(int row, int chunk) {
    return (uint32_t)(row * 64 + ((chunk ^ ((row >> 1) & 3)) * 16));
}

__global__ __launch_bounds__(256, 2) void k_mm(
    const __nv_bfloat16* __restrict__ Ah, const __nv_bfloat16* __restrict__ Al,
    const __nv_bfloat16* __restrict__ Wh, const __nv_bfloat16* __restrict__ Wl,
    float* __restrict__ C, int M, int KP, int Nc)
{
    extern __shared__ __nv_bfloat16 smem[];
    uint32_t sb = sm_u32(smem);
    int tid = threadIdx.x, lane = tid & 31, wid = tid >> 5;
    int wm = wid >> 2, wn = wid & 3;
    int m0 = blockIdx.y * 128, n0 = blockIdx.x * 128;
    const int NC = KP >> 5;
    int lr = lane >> 2, lc = (lane & 3) * 2;

    int rbA = wm * 64 + (lane & 15);
    int csA = lane >> 4;
    uint32_t offA0 = swzo(rbA, csA);
    uint32_t offA1 = swzo(rbA, 2 + csA);
    int rbB = wn * 32 + (lane & 7) + ((lane >> 4) & 1) * 8;
    int csB = (lane >> 3) & 1;
    uint32_t offB[2][2];
    #pragma unroll
    for (int kh = 0; kh < 2; kh++)
        #pragma unroll
        for (int nfp = 0; nfp < 2; nfp++)
            offB[kh][nfp] = swzo(rbB + nfp * 16, csB + kh * 2);

    int row = tid >> 1;
    int q0 = (tid & 1) * 2;
    int gm = m0 + row;
    int aok = (gm < M) ? 16 : 0;
    int gmc = (gm < M) ? gm : (M - 1);
    const __nv_bfloat16* pAh = Ah + (size_t)gmc * KP + q0 * 8;
    const __nv_bfloat16* pAl = Al + (size_t)gmc * KP + q0 * 8;
    const __nv_bfloat16* pBh = Wh + (size_t)(n0 + row) * KP + q0 * 8;
    const __nv_bfloat16* pBl = Wl + (size_t)(n0 + row) * KP + q0 * 8;
    uint32_t dro0 = swzo(row, q0);
    uint32_t dro1 = swzo(row, q0 + 1);

    auto issue = [&](int c) {
        int k0 = c << 5;
        uint32_t st = sb + (uint32_t)(c % PIPE) * STAGE_B;
        cp16(st + dro0,              pAh + k0,     aok);
        cp16(st + dro1,              pAh + k0 + 8, aok);
        cp16(st + TILE_B + dro0,     pAl + k0,     aok);
        cp16(st + TILE_B + dro1,     pAl + k0 + 8, aok);
        cp16(st + 2*TILE_B + dro0,   pBh + k0,     16);
        cp16(st + 2*TILE_B + dro1,   pBh + k0 + 8, 16);
        cp16(st + 3*TILE_B + dro0,   pBl + k0,     16);
        cp16(st + 3*TILE_B + dro1,   pBl + k0 + 8, 16);
    };

    float acc[4][4][4];
    #pragma unroll
    for (int i = 0; i < 4; i++)
        #pragma unroll
        for (int j = 0; j < 4; j++)
            #pragma unroll
            for (int r = 0; r < 4; r++) acc[i][j][r] = 0.f;

    issue(0);
    asm volatile("cp.async.commit_group;");
    issue(1);
    asm volatile("cp.async.commit_group;");

    for (int c = 0; c < NC; c++) {
        asm volatile("cp.async.wait_group 1;");
        __syncthreads();
        if (c + 2 < NC) issue(c + 2);
        asm volatile("cp.async.commit_group;");

        uint32_t stb = sb + (uint32_t)(c % PIPE) * STAGE_B;

        #pragma unroll
        for (int kh = 0; kh < 2; kh++) {
            uint32_t oA = kh ? offA1 : offA0;
            uint32_t bh[4][2], bl[4][2];
            #pragma unroll
            for (int nfp = 0; nfp < 2; nfp++) {
                uint32_t t[4];
                ldm_x4(t, stb + 2*TILE_B + offB[kh][nfp]);
                bh[2*nfp][0] = t[0]; bh[2*nfp][1] = t[1];
                bh[2*nfp+1][0] = t[2]; bh[2*nfp+1][1] = t[3];
                ldm_x4(t, stb + 3*TILE_B + offB[kh][nfp]);
                bl[2*nfp][0] = t[0]; bl[2*nfp][1] = t[1];
                bl[2*nfp+1][0] = t[2]; bl[2*nfp+1][1] = t[3];
            }
            #pragma unroll
            for (int mf = 0; mf < 4; mf++) {
                uint32_t mo = (uint32_t)mf * 1024;
                uint32_t ah[4], al[4];
                ldm_x4(ah, stb + oA + mo);
                ldm_x4(al, stb + TILE_B + oA + mo);
                #pragma unroll
                for (int nf = 0; nf < 4; nf++) {
                    mma_bf16(acc[mf][nf], ah, bh[nf]);
                    mma_bf16(acc[mf][nf], ah, bl[nf]);
                    mma_bf16(acc[mf][nf], al, bh[nf]);
                }
            }
        }
    }

    #pragma unroll
    for (int mf = 0; mf < 4; mf++) {
        int r0 = m0 + wm * 64 + mf * 16 + lr;
        #pragma unroll
        for (int nf = 0; nf < 4; nf++) {
            int cc = n0 + wn * 32 + nf * 8 + lc;
            if (r0 < M)
                *(float2*)(C + (size_t)r0 * Nc + cc) =
                    make_float2(acc[mf][nf][0], acc[mf][nf][1]);
            if (r0 + 8 < M)
                *(float2*)(C + (size_t)(r0 + 8) * Nc + cc) =
                    make_float2(acc[mf][nf][2], acc[mf][nf][3]);
        }
    }
}

// ---------------- aggregation -> bf16 hi/lo (layers 1-4) ---------------------
__global__ void k_aggv(const float4* __restrict__ h, const float4* __restrict__ bias,
                       __nv_bfloat162* __restrict__ oh, __nv_bfloat162* __restrict__ ol,
                       int relu)
{
    int node = blockIdx.x;
    int t = threadIdx.x;
    int F4 = blockDim.x;
    float dd = g_dis[node];
    float w0 = dd * dd;
    float4 a = h[(size_t)node * F4 + t];
    float4 acc = make_float4(a.x * w0, a.y * w0, a.z * w0, a.w * w0);
    int e = g_off[node], end = g_off[node + 1];
    for (; e + 3 < end; e += 4) {
        int s0 = g_csr[e], s1 = g_csr[e+1], s2 = g_csr[e+2], s3 = g_csr[e+3];
        float u0 = g_nrm[e], u1 = g_nrm[e+1], u2 = g_nrm[e+2], u3 = g_nrm[e+3];
        float4 v0 = h[(size_t)s0 * F4 + t];
        float4 v1 = h[(size_t)s1 * F4 + t];
        float4 v2 = h[(size_t)s2 * F4 + t];
        float4 v3 = h[(size_t)s3 * F4 + t];
        acc.x = fmaf(v0.x, u0, fmaf(v1.x, u1, fmaf(v2.x, u2, fmaf(v3.x, u3, acc.x))));
        acc.y = fmaf(v0.y, u0, fmaf(v1.y, u1, fmaf(v2.y, u2, fmaf(v3.y, u3, acc.y))));
        acc.z = fmaf(v0.z, u0, fmaf(v1.z, u1, fmaf(v2.z, u2, fmaf(v3.z, u3, acc.z))));
        acc.w = fmaf(v0.w, u0, fmaf(v1.w, u1, fmaf(v2.w, u2, fmaf(v3.w, u3, acc.w))));
    }
    for (; e < end; e++) {
        int s0 = g_csr[e];
        float u0 = g_nrm[e];
        float4 v0 = h[(size_t)s0 * F4 + t];
        acc.x = fmaf(v0.x, u0, acc.x);
        acc.y = fmaf(v0.y, u0, acc.y);
        acc.z = fmaf(v0.z, u0, acc.z);
        acc.w = fmaf(v0.w, u0, acc.w);
    }
    float4 bb = bias[t];
    float4 r = make_float4(acc.x + bb.x, acc.y + bb.y, acc.z + bb.z, acc.w + bb.w);
    if (relu) {
        r.x = fmaxf(r.x, 0.f); r.y = fmaxf(r.y, 0.f);
        r.z = fmaxf(r.z, 0.f); r.w = fmaxf(r.w, 0.f);
    }
    __nv_bfloat162 h0, h1, l0, l1;
    h0.x = __float2bfloat16_rn(r.x); h0.y = __float2bfloat16_rn(r.y);
    h1.x = __float2bfloat16_rn(r.z); h1.y = __float2bfloat16_rn(r.w);
    l0.x = __float2bfloat16_rn(r.x - __bfloat162float(h0.x));
    l0.y = __float2bfloat16_rn(r.y - __bfloat162float(h0.y));
    l1.x = __float2bfloat16_rn(r.z - __bfloat162float(h1.x));
    l1.y = __float2bfloat16_rn(r.w - __bfloat162float(h1.y));
    size_t o = ((size_t)node * F4 + t) * 2;
    oh[o] = h0; oh[o + 1] = h1;
    ol[o] = l0; ol[o + 1] = l1;
}

// ---------------- fused layer-5 agg + relu + layer-6 GEMM --------------------
__global__ __launch_bounds__(256) void k_agg5(
    const float4* __restrict__ h, const float4* __restrict__ bias,
    const float* __restrict__ W6, float* __restrict__ S)
{
    __shared__ float Wt[10 * 128];            // Wt[n*128 + k] = W6[k*10 + n]
    for (int i = threadIdx.x; i < 1280; i += 256) {
        int n = i >> 7, k = i & 127;
        Wt[i] = W6[k * 10 + n];
    }
    __syncthreads();

    int w = threadIdx.x >> 5, lane = threadIdx.x & 31;
    int node = blockIdx.x * 8 + w;
    if (node >= NN) return;

    float dd = g_dis[node];
    float w0 = dd * dd;
    float4 a = h[(size_t)node * 32 + lane];
    float4 acc = make_float4(a.x * w0, a.y * w0, a.z * w0, a.w * w0);
    int e = g_off[node], end = g_off[node + 1];
    for (; e + 3 < end; e += 4) {
        int s0 = g_csr[e], s1 = g_csr[e+1], s2 = g_csr[e+2], s3 = g_csr[e+3];
        float u0 = g_nrm[e], u1 = g_nrm[e+1], u2 = g_nrm[e+2], u3 = g_nrm[e+3];
        float4 v0 = h[(size_t)s0 * 32 + lane];
        float4 v1 = h[(size_t)s1 * 32 + lane];
        float4 v2 = h[(size_t)s2 * 32 + lane];
        float4 v3 = h[(size_t)s3 * 32 + lane];
        acc.x = fmaf(v0.x, u0, fmaf(v1.x, u1, fmaf(v2.x, u2, fmaf(v3.x, u3, acc.x))));
        acc.y = fmaf(v0.y, u0, fmaf(v1.y, u1, fmaf(v2.y, u2, fmaf(v3.y, u3, acc.y))));
        acc.z = fmaf(v0.z, u0, fmaf(v1.z, u1, fmaf(v2.z, u2, fmaf(v3.z, u3, acc.z))));
        acc.w = fmaf(v0.w, u0, fmaf(v1.w, u1, fmaf(v2.w, u2, fmaf(v3.w, u3, acc.w))));
    }
    for (; e < end; e++) {
        int s0 = g_csr[e];
        float u0 = g_nrm[e];
        float4 v0 = h[(size_t)s0 * 32 + lane];
        acc.x = fmaf(v0.x, u0, acc.x);
        acc.y = fmaf(v0.y, u0, acc.y);
        acc.z = fmaf(v0.z, u0, acc.z);
        acc.w = fmaf(v0.w, u0, acc.w);
    }
    float4 bb = bias[lane];
    float4 r = make_float4(fmaxf(acc.x + bb.x, 0.f), fmaxf(acc.y + bb.y, 0.f),
                           fmaxf(acc.z + bb.z, 0.f), fmaxf(acc.w + bb.w, 0.f));

    float out = 0.f;
    #pragma unroll
    for (int n = 0; n < 10; n++) {
        float4 wv = *(const float4*)(Wt + n * 128 + lane * 4);
        float p = fmaf(r.x, wv.x, fmaf(r.y, wv.y, fmaf(r.z, wv.z, r.w * wv.w)));
        #pragma unroll
        for (int o = 16; o; o >>= 1) p += __shfl_xor_sync(0xFFFFFFFFu, p, o);
        if (lane == n) out = p;
    }
    if (lane < 10) S[(size_t)node * 10 + lane] = out;
}

// ---------------- fused final agg + log_softmax (4 nodes / 128-thr block) ----
__global__ __launch_bounds__(128) void k_tail(
    const float* __restrict__ S, const float* __restrict__ bias,
    float* __restrict__ out)
{
    int w = threadIdx.x >> 5, f = threadIdx.x & 31;
    int node = blockIdx.x * 4 + w;
    if (node >= NN) return;
    bool act = f < 10;
    float dd = g_dis[node];
    float val = 0.f;
    if (act) {
        val = S[(size_t)node * 10 + f] * dd * dd;
        int e = g_off[node], end = g_off[node + 1];
        for (; e < end; e++) {
            int s = g_csr[e];
            val = fmaf(S[(size_t)s * 10 + f], g_nrm[e], val);
        }
        val += bias[f];
    }
    float m = act ? val : -1e30f;
    #pragma unroll
    for (int o = 16; o; o >>= 1) m = fmaxf(m, __shfl_xor_sync(0xFFFFFFFFu, m, o));
    float ex = act ? __expf(val - m) : 0.f;
    #pragma unroll
    for (int o = 16; o; o >>= 1) ex += __shfl_xor_sync(0xFFFFFFFFu, ex, o);
    if (act) out[(size_t)node * 10 + f] = val - m - __logf(ex);
}

// ---------------- driver -----------------------------------------------------
extern "C" void kernel_launch(void* const* d_in, const int* in_sizes, int n_in,
                              void* d_out, int out_size)
{
    const float* x  = (const float*)d_in[0];
    const int*   ei = (const int*)d_in[1];
    const float* W[6]; const float* b[6];
    for (int i = 0; i < 6; i++) {
        W[i] = (const float*)d_in[2 + 2 * i];
        b[i] = (const float*)d_in[3 + 2 * i];
    }

    __nv_bfloat16 *Ah, *Al, *Wh, *Wl;
    float *C, *S;
    cudaGetSymbolAddress((void**)&Ah, g_Ah);
    cudaGetSymbolAddress((void**)&Al, g_Al);
    cudaGetSymbolAddress((void**)&Wh, g_Wh);
    cudaGetSymbolAddress((void**)&Wl, g_Wl);
    cudaGetSymbolAddress((void**)&C,  g_C);
    cudaGetSymbolAddress((void**)&S,  g_S);

    cudaFuncSetAttribute(k_mm, cudaFuncAttributeMaxDynamicSharedMemorySize, SMEM_MM);

    const int dims[7] = {767, 640, 512, 384, 256, 128, 10};
    const int KPs[6]  = {768, 640, 512, 384, 256, 128};
    const int WO[5]   = {0, 491520, 819200, 1015808, 1114112};

    cudaEventRecord(hx.eFork, 0);

    // 1: pad (main)
    k_pad<<<(NN * 192 + 255) / 256, 256>>>(x);

    // 2: weights (s2)
    cudaStreamWaitEvent(hx.s2, hx.eFork, 0);
    WPtrs wp; for (int i = 0; i < 5; i++) wp.p[i] = W[i];
    k_wT_all<<<(WTOT + 255) / 256, 256, 0, hx.s2>>>(wp);
    cudaEventRecord(hx.eWT, hx.s2);

    // 3: CSR zero (s1)
    cudaStreamWaitEvent(hx.s1, hx.eFork, 0);
    k_zero<<<(NN + 255) / 256, 256, 0, hx.s1>>>();

    // 4: layer-1 GEMM (main; overlaps CSR chain)
    cudaStreamWaitEvent(0, hx.eWT, 0);
    {
        dim3 grid(640 / 128, (NN + 127) / 128);
        k_mm<<<grid, 256, SMEM_MM>>>(Ah, Al, Wh + WO[0], Wl + WO[0], C, NN, 768, 640);
    }

    // CSR chain (s1) — overlaps with layer-1 GEMM
    k_hist   <<<(EE + 255) / 256, 256, 0, hx.s1>>>(ei);
    k_scan   <<<1, 1024, 0, hx.s1>>>();
    k_scatter<<<(EE + 255) / 256, 256, 0, hx.s1>>>(ei);
    cudaEventRecord(hx.eCsr, hx.s1);

    // aggregation layer 1 (needs CSR)
    cudaStreamWaitEvent(0, hx.eCsr, 0);
    k_aggv<<<NN, 640 / 4>>>((const float4*)C, (const float4*)b[0],
                            (__nv_bfloat162*)Ah, (__nv_bfloat162*)Al, 1);

    // layers 2-4: GEMM + aggv (hi/lo activations)
    for (int l = 1; l < 4; l++) {
        int F = dims[l + 1], KP = KPs[l];
        dim3 grid(F / 128, (NN + 127) / 128);
        k_mm<<<grid, 256, SMEM_MM>>>(Ah, Al, Wh + WO[l], Wl + WO[l], C, NN, KP, F);
        k_aggv<<<NN, F / 4>>>((const float4*)C, (const float4*)b[l],
                              (__nv_bfloat162*)Ah, (__nv_bfloat162*)Al, 1);
    }
    // layer 5 GEMM (K=256 -> F=128)
    {
        dim3 grid(1, (NN + 127) / 128);
        k_mm<<<grid, 256, SMEM_MM>>>(Ah, Al, Wh + WO[4], Wl + WO[4], C, NN, 256, 128);
    }
    // fused: layer-5 agg + relu + layer-6 GEMM -> S
    k_agg5<<<(NN + 7) / 8, 256>>>((const float4*)C, (const float4*)b[4], W[5], S);
    // final: agg(S) + bias6 + log_softmax
    k_tail<<<(NN + 3) / 4, 128>>>(S, b[5], (float*)d_out);
}